// round 3
// baseline (speedup 1.0000x reference)
#include <cuda_runtime.h>
#include <cstdint>

typedef unsigned long long u64;

// ---- packed f32x2 helpers (Blackwell sm_100+; FFMA2 only reachable via PTX) ----
__device__ __forceinline__ u64 pack2(float lo, float hi) {
    u64 r; asm("mov.b64 %0, {%1, %2};" : "=l"(r) : "f"(lo), "f"(hi)); return r;
}
__device__ __forceinline__ void unpack2(u64 v, float& lo, float& hi) {
    asm("mov.b64 {%0, %1}, %2;" : "=f"(lo), "=f"(hi) : "l"(v));
}
__device__ __forceinline__ u64 sub2(u64 a, u64 b) {
    u64 r; asm("sub.rn.f32x2 %0, %1, %2;" : "=l"(r) : "l"(a), "l"(b)); return r;
}
__device__ __forceinline__ u64 add2(u64 a, u64 b) {
    u64 r; asm("add.rn.f32x2 %0, %1, %2;" : "=l"(r) : "l"(a), "l"(b)); return r;
}
__device__ __forceinline__ u64 fma2(u64 a, u64 b, u64 c) {
    u64 r; asm("fma.rn.f32x2 %0, %1, %2, %3;" : "=l"(r) : "l"(a), "l"(b), "l"(c)); return r;
}

#define L_PATH 256
#define D_CH   8
#define OUT_B  584   // 8 + 64 + 512
#define SLOT   584   // slot layout: S1 @0, S2 @8 ([i][j] row-major), S3 @72 ([p][k], p=8i+j)

// Chen combine: A <- A (x) B, B read from a shared-memory slot.
// Lane layout: i = lane>>2, j0 = (lane&3)*2; lane owns S2[i,j0..j0+1] and
// S3 rows p0=2*lane (i,j0) and p1=2*lane+1 (i,j1), 8 k-values each (packed f32x2).
__device__ __forceinline__ void chen_combine(
    const float* __restrict__ s, int lane, int i, int j0,
    u64 S30[4], u64 S31[4], u64& S2p, u64 S1p[4], float& S1ai)
{
    float S2a0, S2a1; unpack2(S2p, S2a0, S2a1);
    const u64 S2a0p = pack2(S2a0, S2a0);
    const u64 S2a1p = pack2(S2a1, S2a1);
    const u64 S1aip = pack2(S1ai, S1ai);

    ulonglong2 t0 = *reinterpret_cast<const ulonglong2*>(s);
    ulonglong2 t1 = *reinterpret_cast<const ulonglong2*>(s + 4);
    u64 S1bp[4] = {t0.x, t0.y, t1.x, t1.y};

    const float* rj = s + 8 + j0 * 8;
    ulonglong2 u0 = *reinterpret_cast<const ulonglong2*>(rj);
    ulonglong2 u1 = *reinterpret_cast<const ulonglong2*>(rj + 4);
    ulonglong2 v0 = *reinterpret_cast<const ulonglong2*>(rj + 8);
    ulonglong2 v1 = *reinterpret_cast<const ulonglong2*>(rj + 12);
    u64 Bj0[4] = {u0.x, u0.y, u1.x, u1.y};
    u64 Bj1[4] = {v0.x, v0.y, v1.x, v1.y};

    float2 s2bi = *reinterpret_cast<const float2*>(s + 8 + i * 8 + j0);
    float2 s1bj = *reinterpret_cast<const float2*>(s + j0);
    float  s1bi = s[i];

    const float* q = s + 72 + 16 * lane;
    ulonglong2 q0 = *reinterpret_cast<const ulonglong2*>(q);
    ulonglong2 q1 = *reinterpret_cast<const ulonglong2*>(q + 4);
    ulonglong2 q2 = *reinterpret_cast<const ulonglong2*>(q + 8);
    ulonglong2 q3 = *reinterpret_cast<const ulonglong2*>(q + 12);
    u64 Q0[4] = {q0.x, q0.y, q1.x, q1.y};
    u64 Q1[4] = {q2.x, q2.y, q3.x, q3.y};

    // S3 = S3a + S3b + S2a (x) S1b + S1a (x) S2b   (pre-update S2a, S1a)
    #pragma unroll
    for (int kk = 0; kk < 4; ++kk) {
        S30[kk] = add2(S30[kk], Q0[kk]);
        S30[kk] = fma2(S2a0p, S1bp[kk], S30[kk]);
        S30[kk] = fma2(S1aip, Bj0[kk], S30[kk]);
        S31[kk] = add2(S31[kk], Q1[kk]);
        S31[kk] = fma2(S2a1p, S1bp[kk], S31[kk]);
        S31[kk] = fma2(S1aip, Bj1[kk], S31[kk]);
    }
    // S2 = S2a + S2b + S1a (x) S1b
    S2p = add2(S2p, pack2(s2bi.x, s2bi.y));
    S2p = fma2(S1aip, pack2(s1bj.x, s1bj.y), S2p);
    // S1 = S1a + S1b
    #pragma unroll
    for (int kk = 0; kk < 4; ++kk) S1p[kk] = add2(S1p[kk], S1bp[kk]);
    S1ai += s1bi;
}

__device__ __forceinline__ void write_sig(
    float* __restrict__ s, int lane,
    const u64 S30[4], const u64 S31[4], u64 S2p, const u64 S1p[4])
{
    if (lane == 0) {
        *reinterpret_cast<ulonglong2*>(s)     = make_ulonglong2(S1p[0], S1p[1]);
        *reinterpret_cast<ulonglong2*>(s + 4) = make_ulonglong2(S1p[2], S1p[3]);
    }
    *reinterpret_cast<u64*>(s + 8 + 2 * lane) = S2p;
    float* q = s + 72 + 16 * lane;
    *reinterpret_cast<ulonglong2*>(q)      = make_ulonglong2(S30[0], S30[1]);
    *reinterpret_cast<ulonglong2*>(q + 4)  = make_ulonglong2(S30[2], S30[3]);
    *reinterpret_cast<ulonglong2*>(q + 8)  = make_ulonglong2(S31[0], S31[1]);
    *reinterpret_cast<ulonglong2*>(q + 12) = make_ulonglong2(S31[2], S31[3]);
}

// 256 threads = 8 warps = one path split into 8 chunks of 32 (last 31) steps.
__global__ void __launch_bounds__(256, 5)
logsig_kernel(const float* __restrict__ x, float* __restrict__ out, int B)
{
    __shared__ float sig[8][SLOT];   // 18688 B

    const int chunk = threadIdx.x >> 5;
    const int lane  = threadIdx.x & 31;
    const int batch = blockIdx.x;

    const int i  = lane >> 2;
    const int j0 = (lane & 3) << 1;

    const int nsteps = (chunk == 7) ? 31 : 32;
    const float* __restrict__ xb =
        x + (size_t)batch * (L_PATH * D_CH) + (size_t)chunk * 32 * D_CH;

    // =================== chunk signature (Chen recursion) ===================
    ulonglong2 r0 = *reinterpret_cast<const ulonglong2*>(xb);
    ulonglong2 r1 = *reinterpret_cast<const ulonglong2*>(xb + 4);
    u64 xpp0 = r0.x, xpp1 = r0.y, xpp2 = r1.x, xpp3 = r1.y;
    float xpi = xb[i];
    u64 xpj;
    { float2 fj = *reinterpret_cast<const float2*>(xb + j0); xpj = pack2(fj.x, fj.y); }

    float S1i = 0.0f;                       // running S1[i]
    u64 S2p   = 0ull;                       // (S2[i,j0], S2[i,j1])
    u64 S30[4] = {0ull,0ull,0ull,0ull};     // S3[p0][k] pairs
    u64 S31[4] = {0ull,0ull,0ull,0ull};     // S3[p1][k] pairs

    #pragma unroll 2
    for (int t = 1; t <= nsteps; ++t) {
        const float* row = xb + t * D_CH;
        ulonglong2 c0 = *reinterpret_cast<const ulonglong2*>(row);
        ulonglong2 c1 = *reinterpret_cast<const ulonglong2*>(row + 4);
        float xci = row[i];
        u64 xcj;
        { float2 fj = *reinterpret_cast<const float2*>(row + j0); xcj = pack2(fj.x, fj.y); }

        u64 dx0 = sub2(c0.x, xpp0);
        u64 dx1 = sub2(c0.y, xpp1);
        u64 dx2 = sub2(c1.x, xpp2);
        u64 dx3 = sub2(c1.y, xpp3);
        float dxi = xci - xpi;
        u64   dxj = sub2(xcj, xpj);

        // level-3 rank-1 update: t_p = S2[p] + 0.5*dx_j*(S1_i + dx_i/3); S3[p,k] += t_p*dx_k
        float g = fmaf(dxi, (1.0f/3.0f), S1i);
        float c = 0.5f * g;
        u64 tq = fma2(pack2(c, c), dxj, S2p);
        float t0, t1; unpack2(tq, t0, t1);
        u64 t0p = pack2(t0, t0);
        u64 t1p = pack2(t1, t1);
        S30[0] = fma2(t0p, dx0, S30[0]);
        S30[1] = fma2(t0p, dx1, S30[1]);
        S30[2] = fma2(t0p, dx2, S30[2]);
        S30[3] = fma2(t0p, dx3, S30[3]);
        S31[0] = fma2(t1p, dx0, S31[0]);
        S31[1] = fma2(t1p, dx1, S31[1]);
        S31[2] = fma2(t1p, dx2, S31[2]);
        S31[3] = fma2(t1p, dx3, S31[3]);

        // level-2: S2[p] += (S1_i + 0.5*dx_i)*dx_j
        float a = fmaf(dxi, 0.5f, S1i);
        S2p = fma2(pack2(a, a), dxj, S2p);
        S1i += dxi;

        xpp0 = c0.x; xpp1 = c0.y; xpp2 = c1.x; xpp3 = c1.y;
        xpi = xci; xpj = xcj;
    }

    // chunk S1: reload first row (L1/L2 hit) instead of keeping x0 live all loop
    u64 S1p[4];
    {
        ulonglong2 f0 = *reinterpret_cast<const ulonglong2*>(xb);
        ulonglong2 f1 = *reinterpret_cast<const ulonglong2*>(xb + 4);
        S1p[0] = sub2(xpp0, f0.x);
        S1p[1] = sub2(xpp1, f0.y);
        S1p[2] = sub2(xpp2, f1.x);
        S1p[3] = sub2(xpp3, f1.y);
    }

    // ===================== 3-round tree combine via smem =====================
    // R1: odd chunks publish; even combine right neighbor.
    if (chunk & 1)
        write_sig(&sig[chunk][0], lane, S30, S31, S2p, S1p);
    __syncthreads();
    if (!(chunk & 1))
        chen_combine(&sig[chunk + 1][0], lane, i, j0, S30, S31, S2p, S1p, S1i);

    // R2: chunks 2,6 publish combined halves; 0 and 4 combine.
    if (chunk == 2 || chunk == 6)
        write_sig(&sig[chunk][0], lane, S30, S31, S2p, S1p);
    __syncthreads();
    if (chunk == 0)
        chen_combine(&sig[2][0], lane, i, j0, S30, S31, S2p, S1p, S1i);
    if (chunk == 4)
        chen_combine(&sig[6][0], lane, i, j0, S30, S31, S2p, S1p, S1i);

    // R3: chunk 4 publishes sig(4..7); chunk 0 combines -> full signature.
    if (chunk == 4)
        write_sig(&sig[4][0], lane, S30, S31, S2p, S1p);
    __syncthreads();
    if (chunk != 0) return;

    chen_combine(&sig[4][0], lane, i, j0, S30, S31, S2p, S1p, S1i);

    // ======================= epilogue: log() + write =======================
    float S1[8];
    unpack2(S1p[0], S1[0], S1[1]);
    unpack2(S1p[1], S1[2], S1[3]);
    unpack2(S1p[2], S1[4], S1[5]);
    unpack2(S1p[3], S1[6], S1[7]);
    float S2a, S2b; unpack2(S2p, S2a, S2b);

    // publish final S1 + S2 grid to slot 0 for cross-lane reads
    float* s0 = &sig[0][0];
    if (lane == 0) {
        *reinterpret_cast<ulonglong2*>(s0)     = make_ulonglong2(S1p[0], S1p[1]);
        *reinterpret_cast<ulonglong2*>(s0 + 4) = make_ulonglong2(S1p[2], S1p[3]);
    }
    *reinterpret_cast<u64*>(s0 + 8 + 2 * lane) = S2p;
    __syncwarp();

    const float s1i = S1i;                   // == S1[i]
    float2 s1j = *reinterpret_cast<const float2*>(s0 + j0);
    const float s1j0 = s1j.x, s1j1 = s1j.y;

    float* ob = out + (size_t)batch * OUT_B;

    // level 1
    if (lane < 8) ob[lane] = s0[lane];

    // level 2: l2 = S2 - 0.5*S1 (x) S1
    float l2a = fmaf(-0.5f * s1i, s1j0, S2a);
    float l2b = fmaf(-0.5f * s1i, s1j1, S2b);
    *reinterpret_cast<float2*>(ob + 8 + 2 * lane) = make_float2(l2a, l2b);

    // level 3: l3 = S3 - 0.5*(S1 (x) S2 + S2 (x) S1) + (1/3) S1 (x) S1 (x) S1
    const float h  = -0.5f * s1i;
    const float e0 = (1.0f/3.0f) * s1i * s1j0 - 0.5f * S2a;
    const float e1 = (1.0f/3.0f) * s1i * s1j1 - 0.5f * S2b;
    const float* g2 = s0 + 8;

    float l3[16];
    #pragma unroll
    for (int kk = 0; kk < 4; ++kk) {
        float s3a, s3b; unpack2(S30[kk], s3a, s3b);
        int k0 = 2 * kk;
        l3[k0]     = s3a + h * g2[j0*8 + k0]     + e0 * S1[k0];
        l3[k0 + 1] = s3b + h * g2[j0*8 + k0 + 1] + e0 * S1[k0 + 1];
    }
    #pragma unroll
    for (int kk = 0; kk < 4; ++kk) {
        float s3a, s3b; unpack2(S31[kk], s3a, s3b);
        int k0 = 2 * kk;
        l3[8 + k0]     = s3a + h * g2[(j0+1)*8 + k0]     + e1 * S1[k0];
        l3[8 + k0 + 1] = s3b + h * g2[(j0+1)*8 + k0 + 1] + e1 * S1[k0 + 1];
    }

    float* o3 = ob + 72 + 16 * lane;
    #pragma unroll
    for (int v = 0; v < 4; ++v)
        *reinterpret_cast<float4*>(o3 + 4 * v) =
            make_float4(l3[4*v], l3[4*v+1], l3[4*v+2], l3[4*v+3]);
}

extern "C" void kernel_launch(void* const* d_in, const int* in_sizes, int n_in,
                              void* d_out, int out_size)
{
    const float* x = (const float*)d_in[0];
    float* out = (float*)d_out;
    const int B = in_sizes[0] / (L_PATH * D_CH);   // 2048
    logsig_kernel<<<B, 256>>>(x, out, B);          // 1 path per 256-thread block
}

// round 4
// speedup vs baseline: 2.7182x; 2.7182x over previous
#include <cuda_runtime.h>
#include <cstdint>

typedef unsigned long long u64;

// ---- packed f32x2 helpers (Blackwell sm_100+; FFMA2 only reachable via PTX) ----
__device__ __forceinline__ u64 pack2(float lo, float hi) {
    u64 r; asm("mov.b64 %0, {%1, %2};" : "=l"(r) : "f"(lo), "f"(hi)); return r;
}
__device__ __forceinline__ void unpack2(u64 v, float& lo, float& hi) {
    asm("mov.b64 {%0, %1}, %2;" : "=f"(lo), "=f"(hi) : "l"(v));
}
__device__ __forceinline__ u64 sub2(u64 a, u64 b) {
    u64 r; asm("sub.rn.f32x2 %0, %1, %2;" : "=l"(r) : "l"(a), "l"(b)); return r;
}
__device__ __forceinline__ u64 add2(u64 a, u64 b) {
    u64 r; asm("add.rn.f32x2 %0, %1, %2;" : "=l"(r) : "l"(a), "l"(b)); return r;
}
__device__ __forceinline__ u64 fma2(u64 a, u64 b, u64 c) {
    u64 r; asm("fma.rn.f32x2 %0, %1, %2, %3;" : "=l"(r) : "l"(a), "l"(b), "l"(c)); return r;
}

#define L_PATH 256
#define D_CH   8
#define OUT_B  584   // 8 + 64 + 512
#define SLOT   584   // slot: S1 @0, S2 @8 ([i][j] row-major), S3 @72 ([p][k], p=8i+j)
#define PATHS_PER_BLOCK 4
#define SDX_STRIDE 2048          // floats per path in smem dx buffer (255*8=2040 used)

// Chen combine: A <- A (x) B, B read from a shared-memory slot. (verified R2)
__device__ __forceinline__ void chen_combine(
    const float* s, int lane, int i, int j0,
    u64 S30[4], u64 S31[4], u64& S2p, u64 S1p[4], float& S1ai)
{
    float S2a0, S2a1; unpack2(S2p, S2a0, S2a1);
    const u64 S2a0p = pack2(S2a0, S2a0);
    const u64 S2a1p = pack2(S2a1, S2a1);
    const u64 S1aip = pack2(S1ai, S1ai);

    ulonglong2 t0 = *reinterpret_cast<const ulonglong2*>(s);
    ulonglong2 t1 = *reinterpret_cast<const ulonglong2*>(s + 4);
    u64 S1bp[4] = {t0.x, t0.y, t1.x, t1.y};

    const float* rj = s + 8 + j0 * 8;
    ulonglong2 u0 = *reinterpret_cast<const ulonglong2*>(rj);
    ulonglong2 u1 = *reinterpret_cast<const ulonglong2*>(rj + 4);
    ulonglong2 v0 = *reinterpret_cast<const ulonglong2*>(rj + 8);
    ulonglong2 v1 = *reinterpret_cast<const ulonglong2*>(rj + 12);
    u64 Bj0[4] = {u0.x, u0.y, u1.x, u1.y};
    u64 Bj1[4] = {v0.x, v0.y, v1.x, v1.y};

    float2 s2bi = *reinterpret_cast<const float2*>(s + 8 + i * 8 + j0);
    float2 s1bj = *reinterpret_cast<const float2*>(s + j0);
    float  s1bi = s[i];

    const float* q = s + 72 + 16 * lane;
    ulonglong2 q0 = *reinterpret_cast<const ulonglong2*>(q);
    ulonglong2 q1 = *reinterpret_cast<const ulonglong2*>(q + 4);
    ulonglong2 q2 = *reinterpret_cast<const ulonglong2*>(q + 8);
    ulonglong2 q3 = *reinterpret_cast<const ulonglong2*>(q + 12);
    u64 Q0[4] = {q0.x, q0.y, q1.x, q1.y};
    u64 Q1[4] = {q2.x, q2.y, q3.x, q3.y};

    // S3 = S3a + S3b + S2a (x) S1b + S1a (x) S2b   (pre-update S2a, S1a)
    #pragma unroll
    for (int kk = 0; kk < 4; ++kk) {
        S30[kk] = add2(S30[kk], Q0[kk]);
        S30[kk] = fma2(S2a0p, S1bp[kk], S30[kk]);
        S30[kk] = fma2(S1aip, Bj0[kk], S30[kk]);
        S31[kk] = add2(S31[kk], Q1[kk]);
        S31[kk] = fma2(S2a1p, S1bp[kk], S31[kk]);
        S31[kk] = fma2(S1aip, Bj1[kk], S31[kk]);
    }
    S2p = add2(S2p, pack2(s2bi.x, s2bi.y));
    S2p = fma2(S1aip, pack2(s1bj.x, s1bj.y), S2p);
    #pragma unroll
    for (int kk = 0; kk < 4; ++kk) S1p[kk] = add2(S1p[kk], S1bp[kk]);
    S1ai += s1bi;
}

__device__ __forceinline__ void write_sig(
    float* s, int lane,
    const u64 S30[4], const u64 S31[4], u64 S2p, const u64 S1p[4])
{
    if (lane == 0) {
        *reinterpret_cast<ulonglong2*>(s)     = make_ulonglong2(S1p[0], S1p[1]);
        *reinterpret_cast<ulonglong2*>(s + 4) = make_ulonglong2(S1p[2], S1p[3]);
    }
    *reinterpret_cast<u64*>(s + 8 + 2 * lane) = S2p;
    float* q = s + 72 + 16 * lane;
    *reinterpret_cast<ulonglong2*>(q)      = make_ulonglong2(S30[0], S30[1]);
    *reinterpret_cast<ulonglong2*>(q + 4)  = make_ulonglong2(S30[2], S30[3]);
    *reinterpret_cast<ulonglong2*>(q + 8)  = make_ulonglong2(S31[0], S31[1]);
    *reinterpret_cast<ulonglong2*>(q + 12) = make_ulonglong2(S31[2], S31[3]);
}

// 256 threads = 8 warps = 4 paths x 2 half-chunks (128 / 127 steps).
__global__ void __launch_bounds__(256, 4)
logsig_kernel(const float* __restrict__ x, float* __restrict__ out, int B)
{
    __shared__ float sdx[PATHS_PER_BLOCK][SDX_STRIDE];   // 32 KB: dx rows per path
    __shared__ float slot[PATHS_PER_BLOCK][SLOT];        // 9.3 KB: combine slots

    const int tid  = threadIdx.x;
    const int warp = tid >> 5;
    const int lane = tid & 31;
    const int path = warp >> 1;          // 0..3
    const int half = warp & 1;           // 0: steps 0..127, 1: steps 128..254
    const int i  = lane >> 2;
    const int j0 = (lane & 3) << 1;

    const float* __restrict__ xg = x + (size_t)blockIdx.x * (PATHS_PER_BLOCK * L_PATH * D_CH);

    // ============ stage increments dx[t] = x[t+1]-x[t] into smem (coalesced) ============
    // 4 paths x 255 rows x 8 floats = 2040 float4 chunks
    for (int q = tid; q < PATHS_PER_BLOCK * 510; q += 256) {
        int p = q / 510;
        int r = q - p * 510;
        int t = r >> 1;
        int h = (r & 1) << 2;
        const float* src = xg + p * (L_PATH * D_CH) + t * 8 + h;
        float4 b = *reinterpret_cast<const float4*>(src + 8);
        float4 a = *reinterpret_cast<const float4*>(src);
        float4 d = make_float4(b.x - a.x, b.y - a.y, b.z - a.z, b.w - a.w);
        *reinterpret_cast<float4*>(&sdx[p][t * 8 + h]) = d;
    }
    __syncthreads();

    // ======================= chunk signature (Chen recursion) =======================
    const int first  = half * 128;
    const int nsteps = half ? 127 : 128;
    const float* sp = &sdx[path][first * 8];

    float S1i = 0.0f;
    u64 S2p   = 0ull;
    u64 S30[4] = {0ull,0ull,0ull,0ull};
    u64 S31[4] = {0ull,0ull,0ull,0ull};

    #pragma unroll 2
    for (int t = 0; t < nsteps; ++t) {
        const float* row = sp + t * 8;
        ulonglong2 d01 = *reinterpret_cast<const ulonglong2*>(row);
        ulonglong2 d23 = *reinterpret_cast<const ulonglong2*>(row + 4);
        float dxi = row[i];
        float2 dj = *reinterpret_cast<const float2*>(row + j0);
        u64 dxj = pack2(dj.x, dj.y);

        // t_p = S2[p] + dx_j*(0.5*S1_i + dx_i/6);  S3[p,k] += t_p * dx_k
        float m = fmaf(dxi, (1.0f/6.0f), 0.5f * S1i);
        u64 tq = fma2(pack2(m, m), dxj, S2p);
        float t0, t1; unpack2(tq, t0, t1);
        u64 t0p = pack2(t0, t0);
        u64 t1p = pack2(t1, t1);
        S30[0] = fma2(t0p, d01.x, S30[0]);
        S30[1] = fma2(t0p, d01.y, S30[1]);
        S30[2] = fma2(t0p, d23.x, S30[2]);
        S30[3] = fma2(t0p, d23.y, S30[3]);
        S31[0] = fma2(t1p, d01.x, S31[0]);
        S31[1] = fma2(t1p, d01.y, S31[1]);
        S31[2] = fma2(t1p, d23.x, S31[2]);
        S31[3] = fma2(t1p, d23.y, S31[3]);

        // S2[p] += (S1_i + 0.5*dx_i)*dx_j ;  S1_i += dx_i
        float a = fmaf(dxi, 0.5f, S1i);
        S2p = fma2(pack2(a, a), dxj, S2p);
        S1i += dxi;
    }

    // chunk S1 from path endpoints (global x, L2-hit)
    u64 S1p[4];
    {
        const float* xp = xg + path * (L_PATH * D_CH);
        const float* e0 = xp + first * 8;
        const float* e1 = xp + (first + nsteps) * 8;
        ulonglong2 a0 = *reinterpret_cast<const ulonglong2*>(e0);
        ulonglong2 a1 = *reinterpret_cast<const ulonglong2*>(e0 + 4);
        ulonglong2 b0 = *reinterpret_cast<const ulonglong2*>(e1);
        ulonglong2 b1 = *reinterpret_cast<const ulonglong2*>(e1 + 4);
        S1p[0] = sub2(b0.x, a0.x);
        S1p[1] = sub2(b0.y, a0.y);
        S1p[2] = sub2(b1.x, a1.x);
        S1p[3] = sub2(b1.y, a1.y);
    }

    // ===================== single combine round via smem =====================
    if (half)
        write_sig(&slot[path][0], lane, S30, S31, S2p, S1p);
    __syncthreads();
    if (half) return;

    chen_combine(&slot[path][0], lane, i, j0, S30, S31, S2p, S1p, S1i);

    // ======================= epilogue: log() + write =======================
    float S1[8];
    unpack2(S1p[0], S1[0], S1[1]);
    unpack2(S1p[1], S1[2], S1[3]);
    unpack2(S1p[2], S1[4], S1[5]);
    unpack2(S1p[3], S1[6], S1[7]);
    float S2a, S2b; unpack2(S2p, S2a, S2b);

    // publish final S1 + S2 grid to this path's slot for cross-lane reads
    float* s0 = &slot[path][0];
    if (lane == 0) {
        *reinterpret_cast<ulonglong2*>(s0)     = make_ulonglong2(S1p[0], S1p[1]);
        *reinterpret_cast<ulonglong2*>(s0 + 4) = make_ulonglong2(S1p[2], S1p[3]);
    }
    *reinterpret_cast<u64*>(s0 + 8 + 2 * lane) = S2p;
    __syncwarp();

    const float s1i = S1i;                   // == S1[i]
    float2 s1j = *reinterpret_cast<const float2*>(s0 + j0);
    const float s1j0 = s1j.x, s1j1 = s1j.y;

    float* ob = out + ((size_t)blockIdx.x * PATHS_PER_BLOCK + path) * OUT_B;

    // level 1
    if (lane < 8) ob[lane] = s0[lane];

    // level 2: l2 = S2 - 0.5*S1 (x) S1
    float l2a = fmaf(-0.5f * s1i, s1j0, S2a);
    float l2b = fmaf(-0.5f * s1i, s1j1, S2b);
    *reinterpret_cast<float2*>(ob + 8 + 2 * lane) = make_float2(l2a, l2b);

    // level 3: l3 = S3 - 0.5*(S1 (x) S2 + S2 (x) S1) + (1/3) S1 (x) S1 (x) S1
    const float h  = -0.5f * s1i;
    const float e0 = (1.0f/3.0f) * s1i * s1j0 - 0.5f * S2a;
    const float e1 = (1.0f/3.0f) * s1i * s1j1 - 0.5f * S2b;
    const float* g2 = s0 + 8;

    float l3[16];
    #pragma unroll
    for (int kk = 0; kk < 4; ++kk) {
        float s3a, s3b; unpack2(S30[kk], s3a, s3b);
        int k0 = 2 * kk;
        l3[k0]     = s3a + h * g2[j0*8 + k0]     + e0 * S1[k0];
        l3[k0 + 1] = s3b + h * g2[j0*8 + k0 + 1] + e0 * S1[k0 + 1];
    }
    #pragma unroll
    for (int kk = 0; kk < 4; ++kk) {
        float s3a, s3b; unpack2(S31[kk], s3a, s3b);
        int k0 = 2 * kk;
        l3[8 + k0]     = s3a + h * g2[(j0+1)*8 + k0]     + e1 * S1[k0];
        l3[8 + k0 + 1] = s3b + h * g2[(j0+1)*8 + k0 + 1] + e1 * S1[k0 + 1];
    }

    float* o3 = ob + 72 + 16 * lane;
    #pragma unroll
    for (int v = 0; v < 4; ++v)
        *reinterpret_cast<float4*>(o3 + 4 * v) =
            make_float4(l3[4*v], l3[4*v+1], l3[4*v+2], l3[4*v+3]);
}

extern "C" void kernel_launch(void* const* d_in, const int* in_sizes, int n_in,
                              void* d_out, int out_size)
{
    const float* x = (const float*)d_in[0];
    float* out = (float*)d_out;
    const int B = in_sizes[0] / (L_PATH * D_CH);   // 2048
    logsig_kernel<<<B / PATHS_PER_BLOCK, 256>>>(x, out, B);
}

// round 5
// speedup vs baseline: 2.9363x; 1.0803x over previous
#include <cuda_runtime.h>
#include <cstdint>

typedef unsigned long long u64;

// ---- packed f32x2 helpers (Blackwell sm_100+; FFMA2 only reachable via PTX) ----
__device__ __forceinline__ u64 pack2(float lo, float hi) {
    u64 r; asm("mov.b64 %0, {%1, %2};" : "=l"(r) : "f"(lo), "f"(hi)); return r;
}
__device__ __forceinline__ void unpack2(u64 v, float& lo, float& hi) {
    asm("mov.b64 {%0, %1}, %2;" : "=f"(lo), "=f"(hi) : "l"(v));
}
__device__ __forceinline__ u64 sub2(u64 a, u64 b) {
    u64 r; asm("sub.rn.f32x2 %0, %1, %2;" : "=l"(r) : "l"(a), "l"(b)); return r;
}
__device__ __forceinline__ u64 add2(u64 a, u64 b) {
    u64 r; asm("add.rn.f32x2 %0, %1, %2;" : "=l"(r) : "l"(a), "l"(b)); return r;
}
__device__ __forceinline__ u64 fma2(u64 a, u64 b, u64 c) {
    u64 r; asm("fma.rn.f32x2 %0, %1, %2, %3;" : "=l"(r) : "l"(a), "l"(b), "l"(c)); return r;
}

#define L_PATH 256
#define D_CH   8
#define OUT_B  584   // 8 + 64 + 512
#define SLOT   584   // slot: S1 @0, S2 @8 ([i][j] row-major), S3 @72 ([p][k], p=8i+j)
#define PATHS_PER_BLOCK 2
#define NTHREADS 128
#define SDX_STRIDE 2048          // floats per path in smem dx buffer (255*8=2040 used)

// Chen combine: A <- A (x) B, B read from a shared-memory slot.
__device__ __forceinline__ void chen_combine(
    const float* s, int lane, int i, int j0,
    u64 S30[4], u64 S31[4], u64& S2p, u64 S1p[4], float& S1ai)
{
    float S2a0, S2a1; unpack2(S2p, S2a0, S2a1);
    const u64 S2a0p = pack2(S2a0, S2a0);
    const u64 S2a1p = pack2(S2a1, S2a1);
    const u64 S1aip = pack2(S1ai, S1ai);

    ulonglong2 t0 = *reinterpret_cast<const ulonglong2*>(s);
    ulonglong2 t1 = *reinterpret_cast<const ulonglong2*>(s + 4);
    u64 S1bp[4] = {t0.x, t0.y, t1.x, t1.y};

    const float* rj = s + 8 + j0 * 8;
    ulonglong2 u0 = *reinterpret_cast<const ulonglong2*>(rj);
    ulonglong2 u1 = *reinterpret_cast<const ulonglong2*>(rj + 4);
    ulonglong2 v0 = *reinterpret_cast<const ulonglong2*>(rj + 8);
    ulonglong2 v1 = *reinterpret_cast<const ulonglong2*>(rj + 12);
    u64 Bj0[4] = {u0.x, u0.y, u1.x, u1.y};
    u64 Bj1[4] = {v0.x, v0.y, v1.x, v1.y};

    float2 s2bi = *reinterpret_cast<const float2*>(s + 8 + i * 8 + j0);
    float2 s1bj = *reinterpret_cast<const float2*>(s + j0);
    float  s1bi = s[i];

    const float* q = s + 72 + 16 * lane;
    ulonglong2 q0 = *reinterpret_cast<const ulonglong2*>(q);
    ulonglong2 q1 = *reinterpret_cast<const ulonglong2*>(q + 4);
    ulonglong2 q2 = *reinterpret_cast<const ulonglong2*>(q + 8);
    ulonglong2 q3 = *reinterpret_cast<const ulonglong2*>(q + 12);
    u64 Q0[4] = {q0.x, q0.y, q1.x, q1.y};
    u64 Q1[4] = {q2.x, q2.y, q3.x, q3.y};

    // S3 = S3a + S3b + S2a (x) S1b + S1a (x) S2b   (pre-update S2a, S1a)
    #pragma unroll
    for (int kk = 0; kk < 4; ++kk) {
        S30[kk] = add2(S30[kk], Q0[kk]);
        S30[kk] = fma2(S2a0p, S1bp[kk], S30[kk]);
        S30[kk] = fma2(S1aip, Bj0[kk], S30[kk]);
        S31[kk] = add2(S31[kk], Q1[kk]);
        S31[kk] = fma2(S2a1p, S1bp[kk], S31[kk]);
        S31[kk] = fma2(S1aip, Bj1[kk], S31[kk]);
    }
    S2p = add2(S2p, pack2(s2bi.x, s2bi.y));
    S2p = fma2(S1aip, pack2(s1bj.x, s1bj.y), S2p);
    #pragma unroll
    for (int kk = 0; kk < 4; ++kk) S1p[kk] = add2(S1p[kk], S1bp[kk]);
    S1ai += s1bi;
}

__device__ __forceinline__ void write_sig(
    float* s, int lane,
    const u64 S30[4], const u64 S31[4], u64 S2p, const u64 S1p[4])
{
    if (lane == 0) {
        *reinterpret_cast<ulonglong2*>(s)     = make_ulonglong2(S1p[0], S1p[1]);
        *reinterpret_cast<ulonglong2*>(s + 4) = make_ulonglong2(S1p[2], S1p[3]);
    }
    *reinterpret_cast<u64*>(s + 8 + 2 * lane) = S2p;
    float* q = s + 72 + 16 * lane;
    *reinterpret_cast<ulonglong2*>(q)      = make_ulonglong2(S30[0], S30[1]);
    *reinterpret_cast<ulonglong2*>(q + 4)  = make_ulonglong2(S30[2], S30[3]);
    *reinterpret_cast<ulonglong2*>(q + 8)  = make_ulonglong2(S31[0], S31[1]);
    *reinterpret_cast<ulonglong2*>(q + 12) = make_ulonglong2(S31[2], S31[3]);
}

// 128 threads = 4 warps = 2 paths x 2 half-chunks (128 / 127 steps).
__global__ void __launch_bounds__(NTHREADS, 8)
logsig_kernel(const float* __restrict__ x, float* __restrict__ out, int B)
{
    __shared__ float sdx[PATHS_PER_BLOCK][SDX_STRIDE];   // 16 KB: dx rows per path
    __shared__ float slot[PATHS_PER_BLOCK][SLOT];        // 4.7 KB: combine slots

    const int tid  = threadIdx.x;
    const int warp = tid >> 5;
    const int lane = tid & 31;
    const int path = warp >> 1;          // 0..1
    const int half = warp & 1;           // 0: steps 0..127, 1: steps 128..254
    const int i  = lane >> 2;
    const int j0 = (lane & 3) << 1;

    const float* __restrict__ xg = x + (size_t)blockIdx.x * (PATHS_PER_BLOCK * L_PATH * D_CH);

    // ============ stage increments dx[t] = x[t+1]-x[t] into smem (coalesced) ============
    for (int q = tid; q < PATHS_PER_BLOCK * 510; q += NTHREADS) {
        int p = q / 510;
        int r = q - p * 510;
        int t = r >> 1;
        int h = (r & 1) << 2;
        const float* src = xg + p * (L_PATH * D_CH) + t * 8 + h;
        float4 b = *reinterpret_cast<const float4*>(src + 8);
        float4 a = *reinterpret_cast<const float4*>(src);
        float4 d = make_float4(b.x - a.x, b.y - a.y, b.z - a.z, b.w - a.w);
        *reinterpret_cast<float4*>(&sdx[p][t * 8 + h]) = d;
    }
    __syncthreads();

    // ======================= chunk signature (Chen recursion) =======================
    const int first  = half * 128;
    const int nsteps = half ? 127 : 128;
    const float* sp = &sdx[path][first * 8];

    // HS = (0.5*S1_i, S1_i) packed; scalar side chain fused into f32x2
    const u64 C_M_A = pack2(1.0f/6.0f, 0.5f);   // makes (m, a)
    const u64 C_UPD = pack2(0.5f, 1.0f);        // updates (h, S1_i)
    u64 HS    = 0ull;
    u64 S2p   = 0ull;
    u64 S30[4] = {0ull,0ull,0ull,0ull};
    u64 S31[4] = {0ull,0ull,0ull,0ull};

    #pragma unroll 2
    for (int t = 0; t < nsteps; ++t) {
        const float* row = sp + t * 8;
        ulonglong2 d01 = *reinterpret_cast<const ulonglong2*>(row);
        ulonglong2 d23 = *reinterpret_cast<const ulonglong2*>(row + 4);
        float dxi = row[i];
        float2 dj = *reinterpret_cast<const float2*>(row + j0);
        u64 dxj = pack2(dj.x, dj.y);
        u64 dxii = pack2(dxi, dxi);

        // (m, a) = (h + dxi/6, S1_i + dxi/2)
        u64 MA = fma2(dxii, C_M_A, HS);
        float m, a; unpack2(MA, m, a);

        // t_p = S2[p] + m*dx_j ;  S3[p,k] += t_p * dx_k
        u64 tq = fma2(pack2(m, m), dxj, S2p);
        float t0, t1; unpack2(tq, t0, t1);
        u64 t0p = pack2(t0, t0);
        u64 t1p = pack2(t1, t1);
        S30[0] = fma2(t0p, d01.x, S30[0]);
        S30[1] = fma2(t0p, d01.y, S30[1]);
        S30[2] = fma2(t0p, d23.x, S30[2]);
        S30[3] = fma2(t0p, d23.y, S30[3]);
        S31[0] = fma2(t1p, d01.x, S31[0]);
        S31[1] = fma2(t1p, d01.y, S31[1]);
        S31[2] = fma2(t1p, d23.x, S31[2]);
        S31[3] = fma2(t1p, d23.y, S31[3]);

        // S2[p] += a*dx_j ;  (h, S1_i) += (0.5, 1)*dxi
        S2p = fma2(pack2(a, a), dxj, S2p);
        HS  = fma2(dxii, C_UPD, HS);
    }

    float S1i;
    { float hh; unpack2(HS, hh, S1i); }

    // chunk S1 from path endpoints (global x, L2-hit)
    u64 S1p[4];
    {
        const float* xp = xg + path * (L_PATH * D_CH);
        const float* e0 = xp + first * 8;
        const float* e1 = xp + (first + nsteps) * 8;
        ulonglong2 a0 = *reinterpret_cast<const ulonglong2*>(e0);
        ulonglong2 a1 = *reinterpret_cast<const ulonglong2*>(e0 + 4);
        ulonglong2 b0 = *reinterpret_cast<const ulonglong2*>(e1);
        ulonglong2 b1 = *reinterpret_cast<const ulonglong2*>(e1 + 4);
        S1p[0] = sub2(b0.x, a0.x);
        S1p[1] = sub2(b0.y, a0.y);
        S1p[2] = sub2(b1.x, a1.x);
        S1p[3] = sub2(b1.y, a1.y);
    }

    // ===================== single combine round via smem =====================
    if (half)
        write_sig(&slot[path][0], lane, S30, S31, S2p, S1p);
    __syncthreads();
    if (half) return;

    chen_combine(&slot[path][0], lane, i, j0, S30, S31, S2p, S1p, S1i);

    // ======================= epilogue: log() + write =======================
    float S1[8];
    unpack2(S1p[0], S1[0], S1[1]);
    unpack2(S1p[1], S1[2], S1[3]);
    unpack2(S1p[2], S1[4], S1[5]);
    unpack2(S1p[3], S1[6], S1[7]);
    float S2a, S2b; unpack2(S2p, S2a, S2b);

    // publish final S1 + S2 grid to this path's slot for cross-lane reads
    float* s0 = &slot[path][0];
    if (lane == 0) {
        *reinterpret_cast<ulonglong2*>(s0)     = make_ulonglong2(S1p[0], S1p[1]);
        *reinterpret_cast<ulonglong2*>(s0 + 4) = make_ulonglong2(S1p[2], S1p[3]);
    }
    *reinterpret_cast<u64*>(s0 + 8 + 2 * lane) = S2p;
    __syncwarp();

    const float s1i = S1i;                   // == S1[i]
    float2 s1j = *reinterpret_cast<const float2*>(s0 + j0);
    const float s1j0 = s1j.x, s1j1 = s1j.y;

    float* ob = out + ((size_t)blockIdx.x * PATHS_PER_BLOCK + path) * OUT_B;

    // level 1
    if (lane < 8) ob[lane] = s0[lane];

    // level 2: l2 = S2 - 0.5*S1 (x) S1
    float l2a = fmaf(-0.5f * s1i, s1j0, S2a);
    float l2b = fmaf(-0.5f * s1i, s1j1, S2b);
    *reinterpret_cast<float2*>(ob + 8 + 2 * lane) = make_float2(l2a, l2b);

    // level 3: l3 = S3 - 0.5*(S1 (x) S2 + S2 (x) S1) + (1/3) S1 (x) S1 (x) S1
    const float h  = -0.5f * s1i;
    const float e0 = (1.0f/3.0f) * s1i * s1j0 - 0.5f * S2a;
    const float e1 = (1.0f/3.0f) * s1i * s1j1 - 0.5f * S2b;
    const float* g2 = s0 + 8;

    float l3[16];
    #pragma unroll
    for (int kk = 0; kk < 4; ++kk) {
        float s3a, s3b; unpack2(S30[kk], s3a, s3b);
        int k0 = 2 * kk;
        l3[k0]     = s3a + h * g2[j0*8 + k0]     + e0 * S1[k0];
        l3[k0 + 1] = s3b + h * g2[j0*8 + k0 + 1] + e0 * S1[k0 + 1];
    }
    #pragma unroll
    for (int kk = 0; kk < 4; ++kk) {
        float s3a, s3b; unpack2(S31[kk], s3a, s3b);
        int k0 = 2 * kk;
        l3[8 + k0]     = s3a + h * g2[(j0+1)*8 + k0]     + e1 * S1[k0];
        l3[8 + k0 + 1] = s3b + h * g2[(j0+1)*8 + k0 + 1] + e1 * S1[k0 + 1];
    }

    float* o3 = ob + 72 + 16 * lane;
    #pragma unroll
    for (int v = 0; v < 4; ++v)
        *reinterpret_cast<float4*>(o3 + 4 * v) =
            make_float4(l3[4*v], l3[4*v+1], l3[4*v+2], l3[4*v+3]);
}

extern "C" void kernel_launch(void* const* d_in, const int* in_sizes, int n_in,
                              void* d_out, int out_size)
{
    const float* x = (const float*)d_in[0];
    float* out = (float*)d_out;
    const int B = in_sizes[0] / (L_PATH * D_CH);   // 2048
    logsig_kernel<<<B / PATHS_PER_BLOCK, NTHREADS>>>(x, out, B);
}